// round 17
// baseline (speedup 1.0000x reference)
#include <cuda_runtime.h>
#include <cstdint>

// GraphMessagePassing on GB300 (sm_103a) — linearity-restructured fp32 + CSR
// aggregation (no float atomics).
//
// messages = relu(nf[src]@W1n + ef@W1e + b1) @ w_m2 + b_m2
// agg      = segment_sum(messages, dst)
//          = (segment_sum(relu_part)) @ w_m2 + deg*b_m2            [w_m2 linear]
// out      = relu([nf, agg]@w_u1 + b_u1) @ w_u2 + b_u2
//   with agg@Wu1b = relu_sum@Wc + deg*bc,  Wc = w_m2@w_u1[64:], bc = b_m2@w_u1[64:]
//
// Pipeline:
//  1 zero      : g_cnt, g_cur (int counters)
//  2 prepack   : Wc, bc, k-pair packed weights
//  3 node_pre  : g_pre = nf@w_m1[:64] + b_m1
//  4 hist      : g_cnt[dst]++           (int RED, no-return)
//  5 scan      : g_off = exclusive_scan(g_cnt)   (single block)
//  6 fill      : g_adj[g_off[d]+cur[d]++] = (src, e)
//  7 aggregate : warp-per-node, relu-sum over CSR edges -> g_relu  (NO atomics)
//  8 node      : out = relu(nf@Wu1a + g_relu@Wc + deg*bc + b_u1) @ w_u2 + b_u2

#define MAX_NODES 50000
#define MAX_EDGES 1300000
typedef unsigned long long u64;

// ---------------- device scratch ----------------
__device__ __align__(16) float  g_pre[(size_t)MAX_NODES * 64];
__device__ __align__(16) float  g_relu[(size_t)MAX_NODES * 64];
__device__ __align__(16) int    g_cnt[MAX_NODES + 4];
__device__ __align__(16) int    g_cur[MAX_NODES + 4];
__device__ __align__(16) int    g_off[MAX_NODES + 4];
__device__ __align__(16) int2   g_adj[MAX_EDGES];
__device__ __align__(16) float2 g_w1np[32 * 64];  // w_m1[:64] k-pair packed
__device__ __align__(16) float2 g_u1p[64 * 64];   // [w_u1[:64]; Wc] k-pair packed
__device__ __align__(16) float2 g_u2p[32 * 64];   // w_u2 k-pair packed
__device__ __align__(16) float  g_bc[64];         // b_m2 @ w_u1[64:]

// ---------------- helpers ----------------
__device__ __forceinline__ u64 ffma2(u64 a, u64 b, u64 c) {
    u64 d;
    asm("fma.rn.f32x2 %0, %1, %2, %3;" : "=l"(d) : "l"(a), "l"(b), "l"(c));
    return d;
}
__device__ __forceinline__ u64 pack2(float lo, float hi) {
    return ((u64)__float_as_uint(hi) << 32) | (u64)__float_as_uint(lo);
}
__device__ __forceinline__ float lo2(u64 v) { return __uint_as_float((unsigned)v); }
__device__ __forceinline__ float hi2(u64 v) { return __uint_as_float((unsigned)(v >> 32)); }
__device__ __forceinline__ float hsum(u64 v) { return lo2(v) + hi2(v); }

// ---------------- 1. zero counters ----------------
__global__ void zero_kernel(int n) {
    int i = blockIdx.x * blockDim.x + threadIdx.x;
    if (i < n) { g_cnt[i] = 0; g_cur[i] = 0; }
}

// ---------------- 2. prepack (single block) ----------------
__global__ __launch_bounds__(256) void prepack_kernel(
    const float* __restrict__ w_m1, const float* __restrict__ w_m2,
    const float* __restrict__ b_m2, const float* __restrict__ w_u1,
    const float* __restrict__ w_u2) {
    __shared__ __align__(16) float sA[64 * 64];  // w_m2, then Wc
    __shared__ __align__(16) float sB[64 * 64];  // w_u1 bottom half
    int t = threadIdx.x;

    for (int i = t; i < 1024; i += 256) {
        ((float4*)sA)[i] = ((const float4*)w_m2)[i];
        ((float4*)sB)[i] = ((const float4*)(w_u1 + 64 * 64))[i];
    }
    __syncthreads();

    float wc[16];
#pragma unroll
    for (int i = 0; i < 16; i++) {
        int id = t + 256 * i;
        int k = id >> 6, c = id & 63;
        float acc = 0.f;
        for (int j = 0; j < 64; j++) acc += sA[k * 64 + j] * sB[j * 64 + c];
        wc[i] = acc;
    }
    float bc = 0.f;
    if (t < 64)
        for (int j = 0; j < 64; j++) bc += b_m2[j] * sB[j * 64 + t];
    __syncthreads();
#pragma unroll
    for (int i = 0; i < 16; i++) sA[t + 256 * i] = wc[i];  // sA := Wc
    if (t < 64) g_bc[t] = bc;
    __syncthreads();

    for (int i = t; i < 32 * 64; i += 256) {
        int k2 = i >> 6, c = i & 63;
        g_w1np[i] = make_float2(w_m1[(2 * k2) * 64 + c], w_m1[(2 * k2 + 1) * 64 + c]);
    }
    for (int i = t; i < 64 * 64; i += 256) {
        int k2 = i >> 6, c = i & 63;
        float a, b;
        if (k2 < 32) {
            a = w_u1[(2 * k2) * 64 + c];
            b = w_u1[(2 * k2 + 1) * 64 + c];
        } else {
            a = sA[(2 * k2 - 64) * 64 + c];
            b = sA[(2 * k2 - 63) * 64 + c];
        }
        g_u1p[i] = make_float2(a, b);
    }
    for (int i = t; i < 32 * 64; i += 256) {
        int k2 = i >> 6, c = i & 63;
        g_u2p[i] = make_float2(w_u2[(2 * k2) * 64 + c], w_u2[(2 * k2 + 1) * 64 + c]);
    }
}

// ---------------- 3. node_pre: g_pre = nf @ w_m1[:64] + b_m1 ----------------
__global__ __launch_bounds__(256) void node_pre_kernel(
    const float* __restrict__ nf, const float* __restrict__ b1, int N) {
    __shared__ __align__(16) float As[64 * 68];
    int tid = threadIdx.x;
    int base = blockIdx.x * 64;

    for (int idx = tid; idx < 64 * 16; idx += 256) {
        int r = idx >> 4, q = idx & 15;
        int n = base + r;
        if (n >= N) n = N - 1;
        *(float4*)&As[r * 68 + q * 4] = *(const float4*)&nf[(size_t)n * 64 + q * 4];
    }
    __syncthreads();

    int tc = tid & 15, tr = tid >> 4;
    u64 acc[4][4];
#pragma unroll
    for (int i = 0; i < 4; i++)
#pragma unroll
        for (int j = 0; j < 4; j++) acc[i][j] = 0ull;

    const float* A0 = As + (tr * 4 + 0) * 68;
    const float* A1 = As + (tr * 4 + 1) * 68;
    const float* A2 = As + (tr * 4 + 2) * 68;
    const float* A3 = As + (tr * 4 + 3) * 68;

#pragma unroll 4
    for (int k2 = 0; k2 < 32; ++k2) {
        u64 a[4];
        a[0] = *(const u64*)(A0 + k2 * 2);
        a[1] = *(const u64*)(A1 + k2 * 2);
        a[2] = *(const u64*)(A2 + k2 * 2);
        a[3] = *(const u64*)(A3 + k2 * 2);
        ulonglong2 wa = *(const ulonglong2*)(g_w1np + k2 * 64 + tc * 4);
        ulonglong2 wb = *(const ulonglong2*)(g_w1np + k2 * 64 + tc * 4 + 2);
        u64 w[4] = {wa.x, wa.y, wb.x, wb.y};
#pragma unroll
        for (int i = 0; i < 4; i++) {
            u64 ai = a[i];
#pragma unroll
            for (int j = 0; j < 4; j++) acc[i][j] = ffma2(ai, w[j], acc[i][j]);
        }
    }

    float4 bb = *(const float4*)(b1 + tc * 4);
#pragma unroll
    for (int i = 0; i < 4; i++) {
        int n = base + tr * 4 + i;
        if (n < N) {
            float4 o;
            o.x = hsum(acc[i][0]) + bb.x;
            o.y = hsum(acc[i][1]) + bb.y;
            o.z = hsum(acc[i][2]) + bb.z;
            o.w = hsum(acc[i][3]) + bb.w;
            *(float4*)&g_pre[(size_t)n * 64 + tc * 4] = o;
        }
    }
}

// ---------------- 4. histogram ----------------
__global__ void hist_kernel(const int* __restrict__ dst, int E) {
    int i = blockIdx.x * blockDim.x + threadIdx.x;
    for (int e = i; e < E; e += gridDim.x * blockDim.x)
        atomicAdd(&g_cnt[dst[e]], 1);
}

// ---------------- 5. exclusive scan (single block) ----------------
#define SCAN_T 1024
__global__ __launch_bounds__(SCAN_T) void scan_kernel(int N) {
    __shared__ int s[SCAN_T];
    int tid = threadIdx.x;
    int carry = 0;
    for (int base = 0; base < N; base += SCAN_T * 4) {
        int idx = base + tid * 4;
        int a0 = 0, a1 = 0, a2 = 0, a3 = 0;
        if (idx + 3 < N) {
            int4 v = *(const int4*)&g_cnt[idx];
            a0 = v.x; a1 = v.y; a2 = v.z; a3 = v.w;
        } else {
            if (idx < N) a0 = g_cnt[idx];
            if (idx + 1 < N) a1 = g_cnt[idx + 1];
            if (idx + 2 < N) a2 = g_cnt[idx + 2];
        }
        int local = a0 + a1 + a2 + a3;
        s[tid] = local;
        __syncthreads();
        for (int d = 1; d < SCAN_T; d <<= 1) {
            int t = (tid >= d) ? s[tid - d] : 0;
            __syncthreads();
            s[tid] += t;
            __syncthreads();
        }
        int excl = carry + s[tid] - local;
        if (idx < N) g_off[idx] = excl;
        if (idx + 1 < N) g_off[idx + 1] = excl + a0;
        if (idx + 2 < N) g_off[idx + 2] = excl + a0 + a1;
        if (idx + 3 < N) g_off[idx + 3] = excl + a0 + a1 + a2;
        carry += s[SCAN_T - 1];
        __syncthreads();
    }
    if (tid == 0) g_off[N] = carry;
}

// ---------------- 6. fill adjacency ----------------
__global__ void fill_kernel(const int* __restrict__ src,
                            const int* __restrict__ dst, int E) {
    int i = blockIdx.x * blockDim.x + threadIdx.x;
    for (int e = i; e < E; e += gridDim.x * blockDim.x) {
        int d = dst[e];
        int p = g_off[d] + atomicAdd(&g_cur[d], 1);
        g_adj[p] = make_int2(src[e], e);
    }
}

// ---------------- 7. aggregate: warp per node, no atomics ----------------
__global__ __launch_bounds__(256) void aggregate_kernel(
    const float* __restrict__ ef, const float* __restrict__ w_m1, int N) {
    int gw = (blockIdx.x * 256 + threadIdx.x) >> 5;  // global warp = node
    int lane = threadIdx.x & 31;
    if (gw >= N) return;

    // hoist W1e columns (2 per lane): wk[k] = w_m1[(64+k)*64 + 2*lane .. +1]
    u64 wk[16];
#pragma unroll
    for (int k = 0; k < 16; k++)
        wk[k] = *(const u64*)&w_m1[(64 + k) * 64 + 2 * lane];

    int off0 = g_off[gw], off1 = g_off[gw + 1];
    float accx = 0.f, accy = 0.f;

#pragma unroll 2
    for (int i = off0; i < off1; i++) {
        int2 ae = g_adj[i];                                   // uniform load
        u64 t = *(const u64*)&g_pre[(size_t)ae.x * 64 + 2 * lane];  // coalesced
        float v = ef[(size_t)ae.y * 16 + (lane & 15)];        // 64B line
#pragma unroll
        for (int k = 0; k < 16; k++) {
            float a = __shfl_sync(0xffffffffu, v, k, 16);
            t = ffma2(pack2(a, a), wk[k], t);
        }
        accx += fmaxf(lo2(t), 0.f);
        accy += fmaxf(hi2(t), 0.f);
    }

    *(float2*)&g_relu[(size_t)gw * 64 + 2 * lane] = make_float2(accx, accy);
}

// ---------------- 8. node kernel (update MLP with folded agg) ----------------
__global__ __launch_bounds__(256) void node_kernel(
    const float* __restrict__ nf, const float* __restrict__ b1,
    const float* __restrict__ b2, float* __restrict__ out, int N) {
    extern __shared__ float sm[];
    float* As = sm;             // [64][132]  cols 0..63 nf, 64..127 relu_sum
    float* Hs = sm + 64 * 132;  // [64][68]
    __shared__ float s_deg[64];

    int tid = threadIdx.x;
    int base = blockIdx.x * 64;

    for (int idx = tid; idx < 64 * 32; idx += 256) {
        int r = idx >> 5, q = idx & 31;
        int n = base + r;
        if (n >= N) n = N - 1;
        float4 v;
        if (q < 16) v = *(const float4*)&nf[(size_t)n * 64 + q * 4];
        else        v = *(const float4*)&g_relu[(size_t)n * 64 + (q - 16) * 4];
        *(float4*)&As[r * 132 + q * 4] = v;
    }
    if (tid < 64) {
        int n = base + tid;
        s_deg[tid] = (n < N) ? (float)(g_off[n + 1] - g_off[n]) : 0.f;
    }
    __syncthreads();

    int tc = tid & 15, tr = tid >> 4;
    u64 acc[4][4];
#pragma unroll
    for (int i = 0; i < 4; i++)
#pragma unroll
        for (int j = 0; j < 4; j++) acc[i][j] = 0ull;

    const float* A0 = As + (tr * 4 + 0) * 132;
    const float* A1 = As + (tr * 4 + 1) * 132;
    const float* A2 = As + (tr * 4 + 2) * 132;
    const float* A3 = As + (tr * 4 + 3) * 132;

#pragma unroll 4
    for (int k2 = 0; k2 < 64; ++k2) {
        u64 a[4];
        a[0] = *(const u64*)(A0 + k2 * 2);
        a[1] = *(const u64*)(A1 + k2 * 2);
        a[2] = *(const u64*)(A2 + k2 * 2);
        a[3] = *(const u64*)(A3 + k2 * 2);
        ulonglong2 wa = *(const ulonglong2*)(g_u1p + k2 * 64 + tc * 4);
        ulonglong2 wb = *(const ulonglong2*)(g_u1p + k2 * 64 + tc * 4 + 2);
        u64 w[4] = {wa.x, wa.y, wb.x, wb.y};
#pragma unroll
        for (int i = 0; i < 4; i++) {
            u64 ai = a[i];
#pragma unroll
            for (int j = 0; j < 4; j++) acc[i][j] = ffma2(ai, w[j], acc[i][j]);
        }
    }

    float4 bb1 = *(const float4*)(b1 + tc * 4);
    float4 bcv = *(const float4*)(g_bc + tc * 4);
#pragma unroll
    for (int i = 0; i < 4; i++) {
        float dg = s_deg[tr * 4 + i];
        float4 h;
        h.x = fmaxf(hsum(acc[i][0]) + bb1.x + dg * bcv.x, 0.f);
        h.y = fmaxf(hsum(acc[i][1]) + bb1.y + dg * bcv.y, 0.f);
        h.z = fmaxf(hsum(acc[i][2]) + bb1.z + dg * bcv.z, 0.f);
        h.w = fmaxf(hsum(acc[i][3]) + bb1.w + dg * bcv.w, 0.f);
        *(float4*)(Hs + (tr * 4 + i) * 68 + tc * 4) = h;
    }
    __syncthreads();

#pragma unroll
    for (int i = 0; i < 4; i++)
#pragma unroll
        for (int j = 0; j < 4; j++) acc[i][j] = 0ull;

    const float* H0 = Hs + (tr * 4 + 0) * 68;
    const float* H1 = Hs + (tr * 4 + 1) * 68;
    const float* H2 = Hs + (tr * 4 + 2) * 68;
    const float* H3 = Hs + (tr * 4 + 3) * 68;

#pragma unroll 4
    for (int k2 = 0; k2 < 32; ++k2) {
        u64 a[4];
        a[0] = *(const u64*)(H0 + k2 * 2);
        a[1] = *(const u64*)(H1 + k2 * 2);
        a[2] = *(const u64*)(H2 + k2 * 2);
        a[3] = *(const u64*)(H3 + k2 * 2);
        ulonglong2 wa = *(const ulonglong2*)(g_u2p + k2 * 64 + tc * 4);
        ulonglong2 wb = *(const ulonglong2*)(g_u2p + k2 * 64 + tc * 4 + 2);
        u64 w[4] = {wa.x, wa.y, wb.x, wb.y};
#pragma unroll
        for (int i = 0; i < 4; i++) {
            u64 ai = a[i];
#pragma unroll
            for (int j = 0; j < 4; j++) acc[i][j] = ffma2(ai, w[j], acc[i][j]);
        }
    }

    float4 bb2 = *(const float4*)(b2 + tc * 4);
#pragma unroll
    for (int i = 0; i < 4; i++) {
        int n = base + tr * 4 + i;
        if (n < N) {
            float4 o;
            o.x = hsum(acc[i][0]) + bb2.x;
            o.y = hsum(acc[i][1]) + bb2.y;
            o.z = hsum(acc[i][2]) + bb2.z;
            o.w = hsum(acc[i][3]) + bb2.w;
            *(float4*)&out[(size_t)n * 64 + tc * 4] = o;
        }
    }
}

// ---------------- launch ----------------
extern "C" void kernel_launch(void* const* d_in, const int* in_sizes, int n_in,
                              void* d_out, int out_size) {
    const float* nf   = (const float*)d_in[0];
    const float* ef   = (const float*)d_in[1];
    const int*   ei   = (const int*)d_in[2];
    const float* w_m1 = (const float*)d_in[3];
    const float* b_m1 = (const float*)d_in[4];
    const float* w_m2 = (const float*)d_in[5];
    const float* b_m2 = (const float*)d_in[6];
    const float* w_u1 = (const float*)d_in[7];
    const float* b_u1 = (const float*)d_in[8];
    const float* w_u2 = (const float*)d_in[9];
    const float* b_u2 = (const float*)d_in[10];
    float* out = (float*)d_out;

    int N = in_sizes[0] / 64;
    int E = in_sizes[2] / 2;
    const int* src = ei;
    const int* dst = ei + E;

    const int NODE_SMEM = (64 * 132 + 64 * 68) * 4;  // 51200
    cudaFuncSetAttribute((const void*)node_kernel,
                         cudaFuncAttributeMaxDynamicSharedMemorySize, NODE_SMEM);

    zero_kernel<<<(N + 255) / 256, 256>>>(N);
    prepack_kernel<<<1, 256>>>(w_m1, w_m2, b_m2, w_u1, w_u2);

    int ntiles = (N + 63) / 64;
    node_pre_kernel<<<ntiles, 256>>>(nf, b_m1, N);

    hist_kernel<<<1024, 256>>>(dst, E);
    scan_kernel<<<1, SCAN_T>>>(N);
    fill_kernel<<<1024, 256>>>(src, dst, E);

    int ablocks = (N * 32 + 255) / 256;
    aggregate_kernel<<<ablocks, 256>>>(ef, w_m1, N);

    node_kernel<<<ntiles, 256, NODE_SMEM>>>(nf, b_u1, b_u2, out, N);
}